// round 4
// baseline (speedup 1.0000x reference)
#include <cuda_runtime.h>
#include <cuda_bf16.h>

#define NROWS 16384          // B*S
#define DIMV  512
#define NQ    8
#define NK    1024
#define NDTOT (NROWS*DIMV)   // 8388608
#define NETOT (NQ*NK*DIMV)   // 4194304

// ------------------------- device scratch (no allocs) ----------------------
__device__ float  g_res[NDTOT];            // fp32 residual
__device__ float  g_enorm[NQ*NK];          // ||e||^2 fp32
__device__ double g_loss_part[NQ*128];     // per-(step,CTA) loss partials
// bf16 3-way splits, stored as uint4 (8 bf16) for vector access
__device__ uint4  g_rh[NDTOT/8], g_rm[NDTOT/8], g_rl[NDTOT/8];
__device__ uint4  g_eh[NETOT/8], g_em[NETOT/8], g_el[NETOT/8];

// ------------------------- PTX helpers (sm_80-compatible only) --------------
__device__ __forceinline__ unsigned smem_u32(const void* p) {
    unsigned a;
    asm("{ .reg .u64 t; cvta.to.shared.u64 t, %1; cvt.u32.u64 %0, t; }"
        : "=r"(a) : "l"(p));
    return a;
}
__device__ __forceinline__ void ldsm4(unsigned* r, unsigned addr) {
    asm volatile("ldmatrix.sync.aligned.m8n8.x4.shared.b16 {%0,%1,%2,%3}, [%4];"
        : "=r"(r[0]), "=r"(r[1]), "=r"(r[2]), "=r"(r[3]) : "r"(addr));
}
__device__ __forceinline__ void mma16816(float* c, const unsigned* a,
                                         unsigned b0, unsigned b1) {
    asm volatile(
        "mma.sync.aligned.m16n8k16.row.col.f32.bf16.bf16.f32 "
        "{%0,%1,%2,%3}, {%4,%5,%6,%7}, {%8,%9}, {%0,%1,%2,%3};"
        : "+f"(c[0]), "+f"(c[1]), "+f"(c[2]), "+f"(c[3])
        : "r"(a[0]), "r"(a[1]), "r"(a[2]), "r"(a[3]), "r"(b0), "r"(b1));
}

// ------------------------- bf16 3-way split ---------------------------------
__device__ __forceinline__ void split3(float v, unsigned short& h,
                                       unsigned short& m, unsigned short& l) {
    __nv_bfloat16 bh = __float2bfloat16(v);
    float fh = __bfloat162float(bh);
    __nv_bfloat16 bm = __float2bfloat16(v - fh);
    float fm = __bfloat162float(bm);
    __nv_bfloat16 bl = __float2bfloat16(v - fh - fm);
    h = *reinterpret_cast<unsigned short*>(&bh);
    m = *reinterpret_cast<unsigned short*>(&bm);
    l = *reinterpret_cast<unsigned short*>(&bl);
}
__device__ __forceinline__ uint2 pack4(const unsigned short* s) {
    return make_uint2((unsigned)s[0] | ((unsigned)s[1] << 16),
                      (unsigned)s[2] | ((unsigned)s[3] << 16));
}

// ------------------------- setup kernels -------------------------------------
__global__ void copy_split_kernel(const float* __restrict__ x) {
    int i = blockIdx.x * blockDim.x + threadIdx.x;       // 0..2097151
    float4 v = reinterpret_cast<const float4*>(x)[i];
    reinterpret_cast<float4*>(g_res)[i] = v;
    unsigned short h[4], m[4], l[4];
    split3(v.x, h[0], m[0], l[0]); split3(v.y, h[1], m[1], l[1]);
    split3(v.z, h[2], m[2], l[2]); split3(v.w, h[3], m[3], l[3]);
    reinterpret_cast<uint2*>(g_rh)[i] = pack4(h);
    reinterpret_cast<uint2*>(g_rm)[i] = pack4(m);
    reinterpret_cast<uint2*>(g_rl)[i] = pack4(l);
}

__global__ void split_emb_kernel(const float* __restrict__ emb) {
    int i = blockIdx.x * blockDim.x + threadIdx.x;       // 0..1048575
    float4 v = reinterpret_cast<const float4*>(emb)[i];
    unsigned short h[4], m[4], l[4];
    split3(v.x, h[0], m[0], l[0]); split3(v.y, h[1], m[1], l[1]);
    split3(v.z, h[2], m[2], l[2]); split3(v.w, h[3], m[3], l[3]);
    reinterpret_cast<uint2*>(g_eh)[i] = pack4(h);
    reinterpret_cast<uint2*>(g_em)[i] = pack4(m);
    reinterpret_cast<uint2*>(g_el)[i] = pack4(l);
}

__global__ void enorm_kernel(const float* __restrict__ emb) {
    int gwarp = (blockIdx.x * blockDim.x + threadIdx.x) >> 5;  // 0..8191
    int lane  = threadIdx.x & 31;
    const float* e = emb + (size_t)gwarp * DIMV;
    float s = 0.f;
    #pragma unroll
    for (int d = lane; d < DIMV; d += 32) { float v = e[d]; s += v * v; }
    #pragma unroll
    for (int off = 16; off > 0; off >>= 1)
        s += __shfl_down_sync(0xffffffffu, s, off);
    if (lane == 0) g_enorm[gwarp] = s;
}

// ------------------------- cp.async stage loader ----------------------------
// Stage s: chunk = s>>3, ktile = s&7. 6 tiles x 16KB. Layout per tile:
// 128 rows x 128 bytes, 16B-column XOR swizzle: col ^ ((row&7)<<4).
__device__ __forceinline__ void issue_stage(int s, int rowBase, int q,
                                            unsigned dynb, int tid) {
    const int chunkI = s >> 3, ktI = s & 7;
    const unsigned buf = dynb + (unsigned)(s & 1) * 98304u;
    const int ebase = q * NK + chunkI * 128;
    #pragma unroll
    for (int j = 0; j < 24; ++j) {
        const int tile = j >> 2;
        const int within = tid + ((j & 3) << 8);   // 0..1023
        const int row = within >> 3, seg = within & 7;
        const uint4* src;
        int gi;
        if (tile == 0)      { src = g_rh; gi = (rowBase + row) * 64 + ktI * 8 + seg; }
        else if (tile == 1) { src = g_rm; gi = (rowBase + row) * 64 + ktI * 8 + seg; }
        else if (tile == 2) { src = g_rl; gi = (rowBase + row) * 64 + ktI * 8 + seg; }
        else {
            src = (tile == 3) ? g_eh : (tile == 4) ? g_em : g_el;
            gi = (ebase + row) * 64 + ktI * 8 + seg;
        }
        unsigned dst = buf + tile * 16384 + row * 128
                     + ((seg * 16) ^ ((row & 7) << 4));
        asm volatile("cp.async.cg.shared.global [%0], [%1], 16;"
                     :: "r"(dst), "l"(src + gi));
    }
}

// ------------------------- HMMA distance + argmin + fused update ------------
// 128 CTAs x 256 threads; CTA: 128 rows x 1024 codes (8 chunks of 128).
// Warp grid 4(M) x 2(N), warp tile 32x64, mma m16n8k16 bf16->fp32, 6 limb
// pairs. After argmin: same CTA updates its own rows' residual + splits,
// accumulates loss partial, writes indices.
__global__ void __launch_bounds__(256, 1) dist_fused_kernel(
    const float* __restrict__ E, float* __restrict__ outF, int q)
{
    extern __shared__ __align__(16) char dsm_raw[];
    __shared__ float sVal[128][2];
    __shared__ int   sIdx[128][2];
    __shared__ int   sFin[128];
    __shared__ double sLoss[8];

    const int tid  = threadIdx.x;
    const int lane = tid & 31;
    const int wid  = tid >> 5;
    const int mw = wid & 3, nw = wid >> 2;
    const int rowBase = blockIdx.x << 7;

    unsigned rawb = smem_u32(dsm_raw);
    unsigned dynb = (rawb + 1023u) & ~1023u;

    const int g = lane >> 2, tig = lane & 3;
    const int rlo = lane & 15, kh = lane >> 4;
    const int mwBase = mw * 32, nwBase = nw * 64;

    // precomputed swizzled row offsets for ldmatrix (colb XORed per use)
    int aRowOff[2], bRowOff[4];
    #pragma unroll
    for (int mi = 0; mi < 2; ++mi) {
        const int row = mwBase + mi * 16 + rlo;
        aRowOff[mi] = row * 128 + ((row & 7) << 4);   // store row*128, keep sw sep
    }
    #pragma unroll
    for (int njp = 0; njp < 4; ++njp) {
        const int row = nwBase + njp * 16 + rlo;
        bRowOff[njp] = row * 128 + ((row & 7) << 4);
    }
    const int aSw[2] = { ((mwBase + 0 * 16 + rlo) & 7) << 4,
                         ((mwBase + 1 * 16 + rlo) & 7) << 4 };
    const int bSw[4] = { ((nwBase + 0 * 16 + rlo) & 7) << 4,
                         ((nwBase + 1 * 16 + rlo) & 7) << 4,
                         ((nwBase + 2 * 16 + rlo) & 7) << 4,
                         ((nwBase + 3 * 16 + rlo) & 7) << 4 };

    float best[2][2];
    int   bidx[2][2];
    #pragma unroll
    for (int a = 0; a < 2; ++a)
        #pragma unroll
        for (int b = 0; b < 2; ++b) { best[a][b] = 3.4e38f; bidx[a][b] = 0; }

    for (int chunk = 0; chunk < 8; ++chunk) {
        float c[2][8][4];
        #pragma unroll
        for (int mi = 0; mi < 2; ++mi)
            #pragma unroll
            for (int nj = 0; nj < 8; ++nj)
                #pragma unroll
                for (int k = 0; k < 4; ++k) c[mi][nj][k] = 0.f;

        for (int kt = 0; kt < 8; ++kt) {
            const int s = chunk * 8 + kt;
            __syncthreads();                        // compute s-1 done (buffer reuse)
            if (s == 0) {
                issue_stage(0, rowBase, q, dynb, tid);
                asm volatile("cp.async.commit_group;" ::: "memory");
            }
            if (s + 1 < 64) {
                issue_stage(s + 1, rowBase, q, dynb, tid);
                asm volatile("cp.async.commit_group;" ::: "memory");
                asm volatile("cp.async.wait_group 1;" ::: "memory");
            } else {
                asm volatile("cp.async.wait_group 0;" ::: "memory");
            }
            __syncthreads();                        // stage s visible to all

            const unsigned stg = dynb + (unsigned)(s & 1) * 98304u;
            #pragma unroll
            for (int k0b = 0; k0b < 4; ++k0b) {
                const int colb = k0b * 32 + kh * 16;

                unsigned Af[3][2][4];
                unsigned Bf[3][4][4];
                #pragma unroll
                for (int l = 0; l < 3; ++l)
                    #pragma unroll
                    for (int mi = 0; mi < 2; ++mi) {
                        const int row = mwBase + mi * 16 + rlo;
                        ldsm4(Af[l][mi], stg + l * 16384 + row * 128
                                        + (colb ^ aSw[mi]));
                    }
                #pragma unroll
                for (int l = 0; l < 3; ++l)
                    #pragma unroll
                    for (int njp = 0; njp < 4; ++njp) {
                        const int row = nwBase + njp * 16 + rlo;
                        ldsm4(Bf[l][njp], stg + (3 + l) * 16384 + row * 128
                                         + (colb ^ bSw[njp]));
                    }

                // 6 limb pairs: (al,bl) in hh, hm, hl, mh, mm, lh
                #pragma unroll
                for (int p = 0; p < 6; ++p) {
                    constexpr int pa[6] = {0, 0, 0, 1, 1, 2};
                    constexpr int pb[6] = {0, 1, 2, 0, 1, 0};
                    const int al = pa[p], bl = pb[p];
                    #pragma unroll
                    for (int mi = 0; mi < 2; ++mi)
                        #pragma unroll
                        for (int nj = 0; nj < 8; ++nj)
                            mma16816(c[mi][nj], Af[al][mi],
                                     Bf[bl][nj >> 1][nj & 1],
                                     Bf[bl][nj >> 1][2 + (nj & 1)]);
                }
            }
        }

        // per-chunk argmin epilogue (ascending col order => first-min tiebreak)
        const float* __restrict__ enp = g_enorm + q * NK + chunk * 128;
        float en[8][2];
        #pragma unroll
        for (int nj = 0; nj < 8; ++nj)
            #pragma unroll
            for (int pc = 0; pc < 2; ++pc)
                en[nj][pc] = enp[nwBase + nj * 8 + 2 * tig + pc];

        #pragma unroll
        for (int mi = 0; mi < 2; ++mi)
            #pragma unroll
            for (int rh = 0; rh < 2; ++rh)
                #pragma unroll
                for (int nj = 0; nj < 8; ++nj)
                    #pragma unroll
                    for (int pc = 0; pc < 2; ++pc) {
                        const float acc = c[mi][nj][rh * 2 + pc];
                        const int colL = nwBase + nj * 8 + 2 * tig + pc;
                        const float d = fmaf(-2.f, acc, en[nj][pc]);
                        if (d < best[mi][rh]) {
                            best[mi][rh] = d;
                            bidx[mi][rh] = chunk * 128 + colL;
                        }
                    }
    }

    // reduce across the 4 tig lanes (same rows, disjoint col sets)
    #pragma unroll
    for (int mi = 0; mi < 2; ++mi)
        #pragma unroll
        for (int rh = 0; rh < 2; ++rh) {
            float v = best[mi][rh];
            int   i = bidx[mi][rh];
            #pragma unroll
            for (int off = 1; off <= 2; off <<= 1) {
                float vo = __shfl_xor_sync(0xffffffffu, v, off);
                int   io = __shfl_xor_sync(0xffffffffu, i, off);
                if (vo < v || (vo == v && io < i)) { v = vo; i = io; }
            }
            if (tig == 0) {
                const int row = mwBase + mi * 16 + rh * 8 + g;
                sVal[row][nw] = v;
                sIdx[row][nw] = i;
            }
        }
    __syncthreads();
    if (tid < 128) {
        float v0 = sVal[tid][0]; int i0 = sIdx[tid][0];
        const float v1 = sVal[tid][1]; const int i1 = sIdx[tid][1];
        if (v1 < v0 || (v1 == v0 && i1 < i0)) { v0 = v1; i0 = i1; }
        sFin[tid] = i0;
        outF[NDTOT + (rowBase + tid) * NQ + q] = (float)i0;
    }
    __syncthreads();

    // ---------------- fused residual update + split refresh + loss ----------
    double ls = 0.0;
    #pragma unroll 1
    for (int rr = 0; rr < 16; ++rr) {
        const int lrow = wid * 16 + rr;
        const int row  = rowBase + lrow;
        const int id   = sFin[lrow];
        float4* r4 = reinterpret_cast<float4*>(g_res + (size_t)row * DIMV);
        const float4* e4 = reinterpret_cast<const float4*>(E + (size_t)id * DIMV);
        #pragma unroll
        for (int j = 0; j < 4; ++j) {
            const int li = lane + 32 * j;
            float4 r = r4[li];
            const float4 e = e4[li];
            r.x -= e.x; r.y -= e.y; r.z -= e.z; r.w -= e.w;
            r4[li] = r;
            ls += (double)(r.x * r.x + r.y * r.y + r.z * r.z + r.w * r.w);

            unsigned short h[4], m[4], l[4];
            split3(r.x, h[0], m[0], l[0]); split3(r.y, h[1], m[1], l[1]);
            split3(r.z, h[2], m[2], l[2]); split3(r.w, h[3], m[3], l[3]);
            const int u2 = row * 128 + li;
            reinterpret_cast<uint2*>(g_rh)[u2] = pack4(h);
            reinterpret_cast<uint2*>(g_rm)[u2] = pack4(m);
            reinterpret_cast<uint2*>(g_rl)[u2] = pack4(l);
        }
    }
    #pragma unroll
    for (int off = 16; off > 0; off >>= 1)
        ls += __shfl_down_sync(0xffffffffu, ls, off);
    if (lane == 0) sLoss[wid] = ls;
    __syncthreads();
    if (tid == 0) {
        double tot = 0.0;
        #pragma unroll
        for (int w = 0; w < 8; ++w) tot += sLoss[w];
        g_loss_part[q * 128 + blockIdx.x] = tot;
    }
}

// ------------------------- finalize -----------------------------------------
__global__ void finalize_kernel(const float* __restrict__ x,
                                float* __restrict__ outF)
{
    const int i = blockIdx.x * blockDim.x + threadIdx.x;
    const float4 xv = reinterpret_cast<const float4*>(x)[i];
    const float4 rv = reinterpret_cast<const float4*>(g_res)[i];
    float4 o;
    o.x = xv.x - rv.x; o.y = xv.y - rv.y;
    o.z = xv.z - rv.z; o.w = xv.w - rv.w;
    reinterpret_cast<float4*>(outF)[i] = o;

    if (blockIdx.x == 0 && threadIdx.x == 0) {
        double tot = 0.0;
        for (int k = 0; k < NQ * 128; ++k) tot += g_loss_part[k];
        outF[NDTOT + NROWS * NQ] = (float)(2.0 * tot / (double)NDTOT);
    }
}

// ---------------------------------------------------------------------------
extern "C" void kernel_launch(void* const* d_in, const int* in_sizes, int n_in,
                              void* d_out, int out_size)
{
    const float* x   = (const float*)d_in[0];
    const float* emb = (const float*)d_in[1];
    float* outF = (float*)d_out;

    cudaFuncSetAttribute(dist_fused_kernel,
                         cudaFuncAttributeMaxDynamicSharedMemorySize, 197632);

    copy_split_kernel<<<8192, 256>>>(x);
    split_emb_kernel<<<4096, 256>>>(emb);
    enorm_kernel<<<1024, 256>>>(emb);

    for (int q = 0; q < NQ; ++q) {
        const float* Eq = emb + (size_t)q * NK * DIMV;
        dist_fused_kernel<<<128, 256, 197632>>>(Eq, outF, q);
    }

    finalize_kernel<<<8192, 256>>>(x, outF);
}